// round 2
// baseline (speedup 1.0000x reference)
#include <cuda_runtime.h>
#include <cstdint>

// Problem constants
#define B_WIN 4096
#define N_TOK 49
#define C_DIM 128
#define H_HEADS 4
#define HD 32
#define M_ROWS (B_WIN * N_TOK)   // 200704 = 1568 * 128 exactly

// Scratch: __device__ globals (no allocations allowed)
__device__ float g_q[B_WIN * H_HEADS * N_TOK * HD];   // [b][h][n][d]
__device__ float g_k[B_WIN * H_HEADS * N_TOK * HD];
__device__ float g_v[B_WIN * H_HEADS * N_TOK * HD];
__device__ float g_ao[(size_t)M_ROWS * C_DIM];        // attention output [b*n][c]

// ---------------------------------------------------------------------------
// QKV GEMM: A = x [M,128], B = qkv_w [128,384]. BlockIdx.y selects q/k/v tile.
// ---------------------------------------------------------------------------
__global__ __launch_bounds__(256) void qkv_gemm(const float* __restrict__ A,
                                                const float* __restrict__ B,
                                                const float* __restrict__ bias) {
    __shared__ float As[32 * 132];  // [k][m], padded stride 132
    __shared__ float Bs[32 * 132];  // [k][n], padded stride 132

    const int tid = threadIdx.x;
    const int tx = tid & 15;
    const int ty = tid >> 4;
    const int m0 = blockIdx.x * 128;
    const int t3 = blockIdx.y;      // 0=q, 1=k, 2=v

    float acc[8][8];
#pragma unroll
    for (int i = 0; i < 8; i++)
#pragma unroll
        for (int j = 0; j < 8; j++) acc[i][j] = 0.0f;

    const float4* A4 = reinterpret_cast<const float4*>(A);
    const float4* B4 = reinterpret_cast<const float4*>(B);

    for (int kc = 0; kc < 128; kc += 32) {
#pragma unroll
        for (int t = 0; t < 4; t++) {
            int flat = tid + t * 256;       // 0..1023 float4s
            int m = flat >> 3;              // 0..127
            int k4 = flat & 7;              // 0..7
            float4 v = A4[(size_t)(m0 + m) * 32 + (kc >> 2) + k4];
            As[(k4 * 4 + 0) * 132 + m] = v.x;
            As[(k4 * 4 + 1) * 132 + m] = v.y;
            As[(k4 * 4 + 2) * 132 + m] = v.z;
            As[(k4 * 4 + 3) * 132 + m] = v.w;
        }
#pragma unroll
        for (int t = 0; t < 4; t++) {
            int flat = tid + t * 256;       // 0..1023
            int kk = flat >> 5;             // 0..31
            int n4 = flat & 31;             // 0..31
            float4 v = B4[(size_t)(kc + kk) * 96 + t3 * 32 + n4];
            *reinterpret_cast<float4*>(&Bs[kk * 132 + n4 * 4]) = v;
        }
        __syncthreads();

#pragma unroll
        for (int kk = 0; kk < 32; kk++) {
            float av[8], bv[8];
            *reinterpret_cast<float4*>(&av[0]) =
                *reinterpret_cast<const float4*>(&As[kk * 132 + ty * 4]);
            *reinterpret_cast<float4*>(&av[4]) =
                *reinterpret_cast<const float4*>(&As[kk * 132 + 64 + ty * 4]);
            *reinterpret_cast<float4*>(&bv[0]) =
                *reinterpret_cast<const float4*>(&Bs[kk * 132 + tx * 4]);
            *reinterpret_cast<float4*>(&bv[4]) =
                *reinterpret_cast<const float4*>(&Bs[kk * 132 + 64 + tx * 4]);
#pragma unroll
            for (int i = 0; i < 8; i++)
#pragma unroll
                for (int j = 0; j < 8; j++) acc[i][j] = fmaf(av[i], bv[j], acc[i][j]);
        }
        __syncthreads();
    }

    // Epilogue: scatter to q/k/v [b][h][n][d]
    float* dst = (t3 == 0) ? g_q : ((t3 == 1) ? g_k : g_v);
    const float scale = (t3 == 0) ? 0.17677669529663687f : 1.0f;  // 32^-0.5

#pragma unroll
    for (int ih = 0; ih < 2; ih++) {
#pragma unroll
        for (int i = 0; i < 4; i++) {
            int r = ih * 64 + ty * 4 + i;
            int gm = m0 + r;
            int b = gm / 49;
            int n = gm - b * 49;
#pragma unroll
            for (int jh = 0; jh < 2; jh++) {
                int c = jh * 64 + tx * 4;
                int h = c >> 5;
                int d = c & 31;
                float4 o;
                o.x = (acc[ih * 4 + i][jh * 4 + 0] + bias[t3 * 128 + c + 0]) * scale;
                o.y = (acc[ih * 4 + i][jh * 4 + 1] + bias[t3 * 128 + c + 1]) * scale;
                o.z = (acc[ih * 4 + i][jh * 4 + 2] + bias[t3 * 128 + c + 2]) * scale;
                o.w = (acc[ih * 4 + i][jh * 4 + 3] + bias[t3 * 128 + c + 3]) * scale;
                *reinterpret_cast<float4*>(
                    &dst[(((size_t)b * H_HEADS + h) * N_TOK + n) * HD + d]) = o;
            }
        }
    }
}

// ---------------------------------------------------------------------------
// Attention: one CTA per (window b, head h). 64 threads.
// idx_stride: 1 if rel_index stored as int32, 2 if int64 (low words).
// ---------------------------------------------------------------------------
__global__ __launch_bounds__(64) void attn_kernel(const float* __restrict__ mask,
                                                  const float* __restrict__ bias_table,
                                                  const int* __restrict__ rel32,
                                                  int idx_stride) {
    __shared__ float qs[56 * 33];
    __shared__ float ks[64 * 33];
    __shared__ float vs[49 * 33];
    __shared__ float S[56 * 65];
    __shared__ float tbl[169];
    __shared__ unsigned short idx_s[2401];

    const int tid = threadIdx.x;
    const int b = blockIdx.x;
    const int h = blockIdx.y;

    for (int i = tid; i < 169; i += 64) tbl[i] = bias_table[i * 4 + h];
    for (int e = tid; e < 2401; e += 64)
        idx_s[e] = (unsigned short)rel32[e * idx_stride];

    const size_t base4 = (((size_t)b * H_HEADS + h) * N_TOK) * 8;  // float4 units
    const float4* q4 = reinterpret_cast<const float4*>(g_q);
    const float4* k4p = reinterpret_cast<const float4*>(g_k);
    const float4* v4 = reinterpret_cast<const float4*>(g_v);
    for (int f = tid; f < 49 * 8; f += 64) {
        int row = f >> 3;
        int c4 = f & 7;
        float4 vq = q4[base4 + f];
        float4 vk = k4p[base4 + f];
        float4 vv = v4[base4 + f];
        int o = row * 33 + c4 * 4;
        qs[o + 0] = vq.x; qs[o + 1] = vq.y; qs[o + 2] = vq.z; qs[o + 3] = vq.w;
        ks[o + 0] = vk.x; ks[o + 1] = vk.y; ks[o + 2] = vk.z; ks[o + 3] = vk.w;
        vs[o + 0] = vv.x; vs[o + 1] = vv.y; vs[o + 2] = vv.z; vs[o + 3] = vv.w;
    }
    for (int i = tid; i < 7 * 32; i += 64) qs[(49 + (i >> 5)) * 33 + (i & 31)] = 0.0f;
    for (int i = tid; i < 15 * 32; i += 64) ks[(49 + (i >> 5)) * 33 + (i & 31)] = 0.0f;
    __syncthreads();

    const int ry = tid >> 3;   // 0..7
    const int cx = tid & 7;    // 0..7
    {
        float acc[7][8];
#pragma unroll
        for (int a = 0; a < 7; a++)
#pragma unroll
            for (int j = 0; j < 8; j++) acc[a][j] = 0.0f;

#pragma unroll 4
        for (int k = 0; k < 32; k++) {
            float qf[7], kf[8];
#pragma unroll
            for (int a = 0; a < 7; a++) qf[a] = qs[(ry * 7 + a) * 33 + k];
#pragma unroll
            for (int j = 0; j < 8; j++) kf[j] = ks[(cx * 8 + j) * 33 + k];
#pragma unroll
            for (int a = 0; a < 7; a++)
#pragma unroll
                for (int j = 0; j < 8; j++) acc[a][j] = fmaf(qf[a], kf[j], acc[a][j]);
        }

        const float* mrow = mask + (size_t)(b & 63) * 2401;
#pragma unroll
        for (int a = 0; a < 7; a++) {
            int n = ry * 7 + a;
            if (n < 49) {
#pragma unroll
                for (int j = 0; j < 8; j++) {
                    int m = cx * 8 + j;
                    if (m < 49) {
                        int e = n * 49 + m;
                        S[n * 65 + m] = acc[a][j] + tbl[idx_s[e]] + mrow[e];
                    }
                }
            }
        }
    }
    __syncthreads();

    if (tid < 49) {
        float mx = -1e30f;
        for (int m = 0; m < 49; m++) mx = fmaxf(mx, S[tid * 65 + m]);
        float s = 0.0f;
        for (int m = 0; m < 49; m++) {
            float e = __expf(S[tid * 65 + m] - mx);
            S[tid * 65 + m] = e;
            s += e;
        }
        float inv = 1.0f / s;
        for (int m = 0; m < 49; m++) S[tid * 65 + m] *= inv;
    } else if (tid < 56) {
        for (int m = 0; m < 49; m++) S[tid * 65 + m] = 0.0f;
    }
    __syncthreads();

    {
        float oacc[7][4];
#pragma unroll
        for (int a = 0; a < 7; a++)
#pragma unroll
            for (int j = 0; j < 4; j++) oacc[a][j] = 0.0f;

#pragma unroll 7
        for (int m = 0; m < 49; m++) {
            float pf[7], vf[4];
#pragma unroll
            for (int a = 0; a < 7; a++) pf[a] = S[(ry * 7 + a) * 65 + m];
#pragma unroll
            for (int j = 0; j < 4; j++) vf[j] = vs[m * 33 + cx * 4 + j];
#pragma unroll
            for (int a = 0; a < 7; a++)
#pragma unroll
                for (int j = 0; j < 4; j++) oacc[a][j] = fmaf(pf[a], vf[j], oacc[a][j]);
        }

#pragma unroll
        for (int a = 0; a < 7; a++) {
            int n = ry * 7 + a;
            if (n < 49) {
                float4 o = make_float4(oacc[a][0], oacc[a][1], oacc[a][2], oacc[a][3]);
                *reinterpret_cast<float4*>(
                    &g_ao[((size_t)b * N_TOK + n) * C_DIM + h * HD + cx * 4]) = o;
            }
        }
    }
}

// ---------------------------------------------------------------------------
// Proj GEMM: A = g_ao [M,128], B = proj_w [128,128], out = d_out [M,128]
// ---------------------------------------------------------------------------
__global__ __launch_bounds__(256) void proj_gemm(const float* __restrict__ B,
                                                 const float* __restrict__ bias,
                                                 float* __restrict__ out) {
    __shared__ float As[32 * 132];
    __shared__ float Bs[32 * 132];

    const int tid = threadIdx.x;
    const int tx = tid & 15;
    const int ty = tid >> 4;
    const int m0 = blockIdx.x * 128;

    float acc[8][8];
#pragma unroll
    for (int i = 0; i < 8; i++)
#pragma unroll
        for (int j = 0; j < 8; j++) acc[i][j] = 0.0f;

    const float4* A4 = reinterpret_cast<const float4*>(g_ao);
    const float4* B4 = reinterpret_cast<const float4*>(B);

    for (int kc = 0; kc < 128; kc += 32) {
#pragma unroll
        for (int t = 0; t < 4; t++) {
            int flat = tid + t * 256;
            int m = flat >> 3;
            int k4 = flat & 7;
            float4 v = A4[(size_t)(m0 + m) * 32 + (kc >> 2) + k4];
            As[(k4 * 4 + 0) * 132 + m] = v.x;
            As[(k4 * 4 + 1) * 132 + m] = v.y;
            As[(k4 * 4 + 2) * 132 + m] = v.z;
            As[(k4 * 4 + 3) * 132 + m] = v.w;
        }
#pragma unroll
        for (int t = 0; t < 4; t++) {
            int flat = tid + t * 256;
            int kk = flat >> 5;
            int n4 = flat & 31;
            float4 v = B4[(size_t)(kc + kk) * 32 + n4];
            *reinterpret_cast<float4*>(&Bs[kk * 132 + n4 * 4]) = v;
        }
        __syncthreads();

#pragma unroll
        for (int kk = 0; kk < 32; kk++) {
            float av[8], bv[8];
            *reinterpret_cast<float4*>(&av[0]) =
                *reinterpret_cast<const float4*>(&As[kk * 132 + ty * 4]);
            *reinterpret_cast<float4*>(&av[4]) =
                *reinterpret_cast<const float4*>(&As[kk * 132 + 64 + ty * 4]);
            *reinterpret_cast<float4*>(&bv[0]) =
                *reinterpret_cast<const float4*>(&Bs[kk * 132 + tx * 4]);
            *reinterpret_cast<float4*>(&bv[4]) =
                *reinterpret_cast<const float4*>(&Bs[kk * 132 + 64 + tx * 4]);
#pragma unroll
            for (int i = 0; i < 8; i++)
#pragma unroll
                for (int j = 0; j < 8; j++) acc[i][j] = fmaf(av[i], bv[j], acc[i][j]);
        }
        __syncthreads();
    }

#pragma unroll
    for (int ih = 0; ih < 2; ih++) {
#pragma unroll
        for (int i = 0; i < 4; i++) {
            int r = ih * 64 + ty * 4 + i;
            size_t gm = (size_t)m0 + r;
#pragma unroll
            for (int jh = 0; jh < 2; jh++) {
                int c = jh * 64 + tx * 4;
                float4 o;
                o.x = acc[ih * 4 + i][jh * 4 + 0] + bias[c + 0];
                o.y = acc[ih * 4 + i][jh * 4 + 1] + bias[c + 1];
                o.z = acc[ih * 4 + i][jh * 4 + 2] + bias[c + 2];
                o.w = acc[ih * 4 + i][jh * 4 + 3] + bias[c + 3];
                *reinterpret_cast<float4*>(&out[gm * C_DIM + c]) = o;
            }
        }
    }
}

// ---------------------------------------------------------------------------
extern "C" void kernel_launch(void* const* d_in, const int* in_sizes, int n_in,
                              void* d_out, int out_size) {
    const float* x          = (const float*)d_in[0];
    const float* mask       = (const float*)d_in[1];
    const float* qkv_w      = (const float*)d_in[2];
    const float* qkv_b      = (const float*)d_in[3];
    const float* proj_w     = (const float*)d_in[4];
    const float* proj_b     = (const float*)d_in[5];
    const float* bias_table = (const float*)d_in[6];
    const int*   rel32      = (const int*)d_in[7];

    // rel_index may be stored as int32 (2401 elems) or int64 (reported 2401
    // elems of 8B -> in_sizes 2401 too, or 4802 int32 words). Detect stride.
    int idx_stride = (in_sizes[7] >= 2401 * 2) ? 2 : 1;

    qkv_gemm<<<dim3(M_ROWS / 128, 3), 256>>>(x, qkv_w, qkv_b);
    attn_kernel<<<dim3(B_WIN, H_HEADS), 64>>>(mask, bias_table, rel32, idx_stride);
    proj_gemm<<<dim3(M_ROWS / 128, 1), 256>>>(proj_w, proj_b, (float*)d_out);
}

// round 3
// speedup vs baseline: 1.1785x; 1.1785x over previous
#include <cuda_runtime.h>
#include <cstdint>

// Problem constants
#define B_WIN 4096
#define N_TOK 49
#define C_DIM 128
#define H_HEADS 4
#define HD 32
#define M_ROWS (B_WIN * N_TOK)   // 200704 = 1568 * 128 exactly

// Scratch: __device__ globals (no allocations allowed)
__device__ float g_q[B_WIN * H_HEADS * N_TOK * HD];   // [b][h][n][d]
__device__ float g_k[B_WIN * H_HEADS * N_TOK * HD];
__device__ float g_v[B_WIN * H_HEADS * N_TOK * HD];
__device__ float g_ao[(size_t)M_ROWS * C_DIM];        // attention output [b*n][c]
__device__ float g_comb[64 * H_HEADS * N_TOK * N_TOK]; // bias+mask [w][h][n][m]

// ---------------------------------------------------------------------------
// comb precompute: comb[w][h][e] = bias_table[rel_index[e]][h] + mask[w][e]
// ---------------------------------------------------------------------------
__global__ void comb_kernel(const float* __restrict__ mask,
                            const float* __restrict__ bias_table,
                            const int* __restrict__ rel32, int idx_stride) {
    const int w = blockIdx.x;
    const int h = blockIdx.y;
    float* dst = g_comb + ((size_t)w * H_HEADS + h) * 2401;
    const float* msk = mask + (size_t)w * 2401;
    for (int e = threadIdx.x; e < 2401; e += blockDim.x) {
        int idx = rel32[e * idx_stride];
        dst[e] = bias_table[idx * H_HEADS + h] + msk[e];
    }
}

// ---------------------------------------------------------------------------
// QKV GEMM: A = x [M,128], B = qkv_w [128,384]. BlockIdx.y selects q/k/v tile.
// ---------------------------------------------------------------------------
__global__ __launch_bounds__(256) void qkv_gemm(const float* __restrict__ A,
                                                const float* __restrict__ B,
                                                const float* __restrict__ bias) {
    __shared__ float As[32 * 132];  // [k][m], padded stride 132
    __shared__ float Bs[32 * 132];  // [k][n], padded stride 132

    const int tid = threadIdx.x;
    const int tx = tid & 15;
    const int ty = tid >> 4;
    const int m0 = blockIdx.x * 128;
    const int t3 = blockIdx.y;      // 0=q, 1=k, 2=v

    float acc[8][8];
#pragma unroll
    for (int i = 0; i < 8; i++)
#pragma unroll
        for (int j = 0; j < 8; j++) acc[i][j] = 0.0f;

    const float4* A4 = reinterpret_cast<const float4*>(A);
    const float4* B4 = reinterpret_cast<const float4*>(B);

    for (int kc = 0; kc < 128; kc += 32) {
#pragma unroll
        for (int t = 0; t < 4; t++) {
            int flat = tid + t * 256;       // 0..1023 float4s
            int m = flat >> 3;              // 0..127
            int k4 = flat & 7;              // 0..7
            float4 v = A4[(size_t)(m0 + m) * 32 + (kc >> 2) + k4];
            As[(k4 * 4 + 0) * 132 + m] = v.x;
            As[(k4 * 4 + 1) * 132 + m] = v.y;
            As[(k4 * 4 + 2) * 132 + m] = v.z;
            As[(k4 * 4 + 3) * 132 + m] = v.w;
        }
#pragma unroll
        for (int t = 0; t < 4; t++) {
            int flat = tid + t * 256;       // 0..1023
            int kk = flat >> 5;             // 0..31
            int n4 = flat & 31;             // 0..31
            float4 v = B4[(size_t)(kc + kk) * 96 + t3 * 32 + n4];
            *reinterpret_cast<float4*>(&Bs[kk * 132 + n4 * 4]) = v;
        }
        __syncthreads();

#pragma unroll
        for (int kk = 0; kk < 32; kk++) {
            float av[8], bv[8];
            *reinterpret_cast<float4*>(&av[0]) =
                *reinterpret_cast<const float4*>(&As[kk * 132 + ty * 4]);
            *reinterpret_cast<float4*>(&av[4]) =
                *reinterpret_cast<const float4*>(&As[kk * 132 + 64 + ty * 4]);
            *reinterpret_cast<float4*>(&bv[0]) =
                *reinterpret_cast<const float4*>(&Bs[kk * 132 + tx * 4]);
            *reinterpret_cast<float4*>(&bv[4]) =
                *reinterpret_cast<const float4*>(&Bs[kk * 132 + 64 + tx * 4]);
#pragma unroll
            for (int i = 0; i < 8; i++)
#pragma unroll
                for (int j = 0; j < 8; j++) acc[i][j] = fmaf(av[i], bv[j], acc[i][j]);
        }
        __syncthreads();
    }

    // Epilogue: scatter to q/k/v [b][h][n][d]
    float* dst = (t3 == 0) ? g_q : ((t3 == 1) ? g_k : g_v);
    const float scale = (t3 == 0) ? 0.17677669529663687f : 1.0f;  // 32^-0.5

#pragma unroll
    for (int ih = 0; ih < 2; ih++) {
#pragma unroll
        for (int i = 0; i < 4; i++) {
            int r = ih * 64 + ty * 4 + i;
            int gm = m0 + r;
            int b = gm / 49;
            int n = gm - b * 49;
#pragma unroll
            for (int jh = 0; jh < 2; jh++) {
                int c = jh * 64 + tx * 4;
                int h = c >> 5;
                int d = c & 31;
                float4 o;
                o.x = (acc[ih * 4 + i][jh * 4 + 0] + bias[t3 * 128 + c + 0]) * scale;
                o.y = (acc[ih * 4 + i][jh * 4 + 1] + bias[t3 * 128 + c + 1]) * scale;
                o.z = (acc[ih * 4 + i][jh * 4 + 2] + bias[t3 * 128 + c + 2]) * scale;
                o.w = (acc[ih * 4 + i][jh * 4 + 3] + bias[t3 * 128 + c + 3]) * scale;
                *reinterpret_cast<float4*>(
                    &dst[(((size_t)b * H_HEADS + h) * N_TOK + n) * HD + d]) = o;
            }
        }
    }
}

// ---------------------------------------------------------------------------
// Attention v2: one CTA per (window b, head h). 128 threads, lean smem.
// Thread grid: rowg = tid>>4 (0..7, 7 rows each -> 56), colg = tid&15 (0..15).
// S phase: cols colg*4 (64). PV phase: cols colg*2 (32).
// Out-of-range accumulators read uninitialized (in-bounds) smem and are
// discarded by write guards -- no zero-padding needed.
// ---------------------------------------------------------------------------
__global__ __launch_bounds__(128) void attn_kernel() {
    __shared__ float qs[56 * 33];    // [n][k]
    __shared__ float ks_t[32 * 68];  // [k][m]  (transposed K)
    __shared__ float vs[49 * 36];    // [m][d]
    __shared__ float S[56 * 53];     // [n][m]

    const int tid = threadIdx.x;
    const int b = blockIdx.x;
    const int h = blockIdx.y;

    // Load q, k, v tiles [49,32]
    const size_t base4 = (((size_t)b * H_HEADS + h) * N_TOK) * 8;  // float4 units
    const float4* q4 = reinterpret_cast<const float4*>(g_q);
    const float4* k4p = reinterpret_cast<const float4*>(g_k);
    const float4* v4 = reinterpret_cast<const float4*>(g_v);
    for (int f = tid; f < 49 * 8; f += 128) {
        int row = f >> 3;
        int c4 = f & 7;
        float4 vq = q4[base4 + f];
        float4 vk = k4p[base4 + f];
        float4 vv = v4[base4 + f];
        int o = row * 33 + c4 * 4;
        qs[o + 0] = vq.x; qs[o + 1] = vq.y; qs[o + 2] = vq.z; qs[o + 3] = vq.w;
        // K transposed: ks_t[k][m]
        ks_t[(c4 * 4 + 0) * 68 + row] = vk.x;
        ks_t[(c4 * 4 + 1) * 68 + row] = vk.y;
        ks_t[(c4 * 4 + 2) * 68 + row] = vk.z;
        ks_t[(c4 * 4 + 3) * 68 + row] = vk.w;
        *reinterpret_cast<float4*>(&vs[row * 36 + c4 * 4]) = vv;
    }
    __syncthreads();

    const int rowg = tid >> 4;   // 0..7  -> rows rowg*7 .. +6
    const int colg = tid & 15;   // 0..15

    // --- S = q k^T : acc[7][4], cols colg*4..+3 ---
    {
        float acc[7][4];
#pragma unroll
        for (int a = 0; a < 7; a++)
#pragma unroll
            for (int j = 0; j < 4; j++) acc[a][j] = 0.0f;

#pragma unroll 4
        for (int k = 0; k < 32; k++) {
            float qf[7];
#pragma unroll
            for (int a = 0; a < 7; a++) qf[a] = qs[(rowg * 7 + a) * 33 + k];
            float4 kf = *reinterpret_cast<const float4*>(&ks_t[k * 68 + colg * 4]);
#pragma unroll
            for (int a = 0; a < 7; a++) {
                acc[a][0] = fmaf(qf[a], kf.x, acc[a][0]);
                acc[a][1] = fmaf(qf[a], kf.y, acc[a][1]);
                acc[a][2] = fmaf(qf[a], kf.z, acc[a][2]);
                acc[a][3] = fmaf(qf[a], kf.w, acc[a][3]);
            }
        }

        const float* cb = g_comb + ((size_t)((b & 63) * H_HEADS + h)) * 2401;
#pragma unroll
        for (int a = 0; a < 7; a++) {
            int n = rowg * 7 + a;
            if (n < 49) {
#pragma unroll
                for (int j = 0; j < 4; j++) {
                    int m = colg * 4 + j;
                    if (m < 49) S[n * 53 + m] = acc[a][j] + cb[n * 49 + m];
                }
            }
        }
    }
    __syncthreads();

    // --- softmax over 49 cols, one thread per row ---
    if (tid < 49) {
        float mx = -1e30f;
#pragma unroll 7
        for (int m = 0; m < 49; m++) mx = fmaxf(mx, S[tid * 53 + m]);
        float s = 0.0f;
#pragma unroll 7
        for (int m = 0; m < 49; m++) {
            float e = __expf(S[tid * 53 + m] - mx);
            S[tid * 53 + m] = e;
            s += e;
        }
        float inv = 1.0f / s;
#pragma unroll 7
        for (int m = 0; m < 49; m++) S[tid * 53 + m] *= inv;
    }
    __syncthreads();

    // --- O = P v : acc2[7][2], cols d = colg*2..+1 ---
    {
        float acc2[7][2];
#pragma unroll
        for (int a = 0; a < 7; a++) { acc2[a][0] = 0.0f; acc2[a][1] = 0.0f; }

#pragma unroll 7
        for (int m = 0; m < 49; m++) {
            float2 vf = *reinterpret_cast<const float2*>(&vs[m * 36 + colg * 2]);
#pragma unroll
            for (int a = 0; a < 7; a++) {
                float pf = S[(rowg * 7 + a) * 53 + m];
                acc2[a][0] = fmaf(pf, vf.x, acc2[a][0]);
                acc2[a][1] = fmaf(pf, vf.y, acc2[a][1]);
            }
        }

#pragma unroll
        for (int a = 0; a < 7; a++) {
            int n = rowg * 7 + a;
            if (n < 49) {
                float2 o = make_float2(acc2[a][0], acc2[a][1]);
                *reinterpret_cast<float2*>(
                    &g_ao[((size_t)b * N_TOK + n) * C_DIM + h * HD + colg * 2]) = o;
            }
        }
    }
}

// ---------------------------------------------------------------------------
// Proj GEMM: A = g_ao [M,128], B = proj_w [128,128], out = d_out [M,128]
// ---------------------------------------------------------------------------
__global__ __launch_bounds__(256) void proj_gemm(const float* __restrict__ B,
                                                 const float* __restrict__ bias,
                                                 float* __restrict__ out) {
    __shared__ float As[32 * 132];
    __shared__ float Bs[32 * 132];

    const int tid = threadIdx.x;
    const int tx = tid & 15;
    const int ty = tid >> 4;
    const int m0 = blockIdx.x * 128;

    float acc[8][8];
#pragma unroll
    for (int i = 0; i < 8; i++)
#pragma unroll
        for (int j = 0; j < 8; j++) acc[i][j] = 0.0f;

    const float4* A4 = reinterpret_cast<const float4*>(g_ao);
    const float4* B4 = reinterpret_cast<const float4*>(B);

    for (int kc = 0; kc < 128; kc += 32) {
#pragma unroll
        for (int t = 0; t < 4; t++) {
            int flat = tid + t * 256;
            int m = flat >> 3;
            int k4 = flat & 7;
            float4 v = A4[(size_t)(m0 + m) * 32 + (kc >> 2) + k4];
            As[(k4 * 4 + 0) * 132 + m] = v.x;
            As[(k4 * 4 + 1) * 132 + m] = v.y;
            As[(k4 * 4 + 2) * 132 + m] = v.z;
            As[(k4 * 4 + 3) * 132 + m] = v.w;
        }
#pragma unroll
        for (int t = 0; t < 4; t++) {
            int flat = tid + t * 256;
            int kk = flat >> 5;
            int n4 = flat & 31;
            float4 v = B4[(size_t)(kc + kk) * 32 + n4];
            *reinterpret_cast<float4*>(&Bs[kk * 132 + n4 * 4]) = v;
        }
        __syncthreads();

#pragma unroll
        for (int kk = 0; kk < 32; kk++) {
            float av[8], bv[8];
            *reinterpret_cast<float4*>(&av[0]) =
                *reinterpret_cast<const float4*>(&As[kk * 132 + ty * 4]);
            *reinterpret_cast<float4*>(&av[4]) =
                *reinterpret_cast<const float4*>(&As[kk * 132 + 64 + ty * 4]);
            *reinterpret_cast<float4*>(&bv[0]) =
                *reinterpret_cast<const float4*>(&Bs[kk * 132 + tx * 4]);
            *reinterpret_cast<float4*>(&bv[4]) =
                *reinterpret_cast<const float4*>(&Bs[kk * 132 + 64 + tx * 4]);
#pragma unroll
            for (int i = 0; i < 8; i++)
#pragma unroll
                for (int j = 0; j < 8; j++) acc[i][j] = fmaf(av[i], bv[j], acc[i][j]);
        }
        __syncthreads();
    }

#pragma unroll
    for (int ih = 0; ih < 2; ih++) {
#pragma unroll
        for (int i = 0; i < 4; i++) {
            int r = ih * 64 + ty * 4 + i;
            size_t gm = (size_t)m0 + r;
#pragma unroll
            for (int jh = 0; jh < 2; jh++) {
                int c = jh * 64 + tx * 4;
                float4 o;
                o.x = acc[ih * 4 + i][jh * 4 + 0] + bias[c + 0];
                o.y = acc[ih * 4 + i][jh * 4 + 1] + bias[c + 1];
                o.z = acc[ih * 4 + i][jh * 4 + 2] + bias[c + 2];
                o.w = acc[ih * 4 + i][jh * 4 + 3] + bias[c + 3];
                *reinterpret_cast<float4*>(&out[gm * C_DIM + c]) = o;
            }
        }
    }
}

// ---------------------------------------------------------------------------
extern "C" void kernel_launch(void* const* d_in, const int* in_sizes, int n_in,
                              void* d_out, int out_size) {
    const float* x          = (const float*)d_in[0];
    const float* mask       = (const float*)d_in[1];
    const float* qkv_w      = (const float*)d_in[2];
    const float* qkv_b      = (const float*)d_in[3];
    const float* proj_w     = (const float*)d_in[4];
    const float* proj_b     = (const float*)d_in[5];
    const float* bias_table = (const float*)d_in[6];
    const int*   rel32      = (const int*)d_in[7];

    int idx_stride = (in_sizes[7] >= 2401 * 2) ? 2 : 1;

    comb_kernel<<<dim3(64, H_HEADS), 256>>>(mask, bias_table, rel32, idx_stride);
    qkv_gemm<<<dim3(M_ROWS / 128, 3), 256>>>(x, qkv_w, qkv_b);
    attn_kernel<<<dim3(B_WIN, H_HEADS), 128>>>();
    proj_gemm<<<dim3(M_ROWS / 128, 1), 256>>>(proj_w, proj_b, (float*)d_out);
}

// round 8
// speedup vs baseline: 1.2519x; 1.0623x over previous
#include <cuda_runtime.h>
#include <cstdint>

// Problem constants
#define B_WIN 4096
#define N_TOK 49
#define C_DIM 128
#define H_HEADS 4
#define HD 32
#define M_ROWS (B_WIN * N_TOK)   // 200704 = 1568 * 128 exactly

// Scratch: __device__ globals (no allocations allowed)
__device__ float g_q[B_WIN * H_HEADS * N_TOK * HD];   // [b][h][n][d]
__device__ float g_k[B_WIN * H_HEADS * N_TOK * HD];
__device__ float g_v[B_WIN * H_HEADS * N_TOK * HD];
__device__ float g_ao[(size_t)M_ROWS * C_DIM];        // attention output [b*n][c]
__device__ float g_comb[64 * H_HEADS * N_TOK * N_TOK]; // bias+mask [w][h][n][m]

// ---------------------------------------------------------------------------
// comb precompute: comb[w][h][e] = bias_table[rel_index[e]][h] + mask[w][e]
// ---------------------------------------------------------------------------
__global__ void comb_kernel(const float* __restrict__ mask,
                            const float* __restrict__ bias_table,
                            const int* __restrict__ rel32, int idx_stride) {
    const int w = blockIdx.x;
    const int h = blockIdx.y;
    float* dst = g_comb + ((size_t)w * H_HEADS + h) * 2401;
    const float* msk = mask + (size_t)w * 2401;
    for (int e = threadIdx.x; e < 2401; e += blockDim.x) {
        int idx = rel32[e * idx_stride];
        dst[e] = bias_table[idx * H_HEADS + h] + msk[e];
    }
}

// ---------------------------------------------------------------------------
// Packed fp32x2 helpers (Blackwell FFMA2). Per-lane math is exact fp32 FMA,
// so results are bit-identical to the scalar version.
// ---------------------------------------------------------------------------
__device__ __forceinline__ unsigned long long pack_dup(float a) {
    unsigned long long r;
    uint32_t ai = __float_as_uint(a);
    asm("mov.b64 %0, {%1, %1};" : "=l"(r) : "r"(ai));
    return r;
}
__device__ __forceinline__ void ffma2(unsigned long long& c, unsigned long long a,
                                      unsigned long long b) {
    asm("fma.rn.f32x2 %0, %1, %2, %0;" : "+l"(c) : "l"(a), "l"(b));
}
__device__ __forceinline__ float lo32(unsigned long long v) {
    return __uint_as_float((uint32_t)v);
}
__device__ __forceinline__ float hi32(unsigned long long v) {
    return __uint_as_float((uint32_t)(v >> 32));
}

// ---------------------------------------------------------------------------
// QKV GEMM (fp32, FFMA2 inner loop): A = x [M,128], B = qkv_w [128,384].
// Same tiling as the proven SGEMM: 128x128 CTA tile, 256 threads, 8x8/thread.
// Accumulators packed as 32 x u64 (col pairs).
// ---------------------------------------------------------------------------
__global__ __launch_bounds__(256) void qkv_gemm(const float* __restrict__ A,
                                                const float* __restrict__ B,
                                                const float* __restrict__ bias) {
    __shared__ float As[32 * 132];  // [k][m], padded stride 132
    __shared__ float Bs[32 * 132];  // [k][n], padded stride 132

    const int tid = threadIdx.x;
    const int tx = tid & 15;
    const int ty = tid >> 4;
    const int m0 = blockIdx.x * 128;
    const int t3 = blockIdx.y;      // 0=q, 1=k, 2=v

    unsigned long long pacc[8][4];
#pragma unroll
    for (int i = 0; i < 8; i++)
#pragma unroll
        for (int j = 0; j < 4; j++) pacc[i][j] = 0ull;

    const float4* A4 = reinterpret_cast<const float4*>(A);
    const float4* B4 = reinterpret_cast<const float4*>(B);

    for (int kc = 0; kc < 128; kc += 32) {
#pragma unroll
        for (int t = 0; t < 4; t++) {
            int flat = tid + t * 256;       // 0..1023 float4s
            int m = flat >> 3;              // 0..127
            int k4 = flat & 7;              // 0..7
            float4 v = A4[(size_t)(m0 + m) * 32 + (kc >> 2) + k4];
            As[(k4 * 4 + 0) * 132 + m] = v.x;
            As[(k4 * 4 + 1) * 132 + m] = v.y;
            As[(k4 * 4 + 2) * 132 + m] = v.z;
            As[(k4 * 4 + 3) * 132 + m] = v.w;
        }
#pragma unroll
        for (int t = 0; t < 4; t++) {
            int flat = tid + t * 256;       // 0..1023
            int kk = flat >> 5;             // 0..31
            int n4 = flat & 31;             // 0..31
            float4 v = B4[(size_t)(kc + kk) * 96 + t3 * 32 + n4];
            *reinterpret_cast<float4*>(&Bs[kk * 132 + n4 * 4]) = v;
        }
        __syncthreads();

#pragma unroll 8
        for (int kk = 0; kk < 32; kk++) {
            float av[8];
            *reinterpret_cast<float4*>(&av[0]) =
                *reinterpret_cast<const float4*>(&As[kk * 132 + ty * 4]);
            *reinterpret_cast<float4*>(&av[4]) =
                *reinterpret_cast<const float4*>(&As[kk * 132 + 64 + ty * 4]);
            unsigned long long bp0 =
                *reinterpret_cast<const unsigned long long*>(&Bs[kk * 132 + tx * 4]);
            unsigned long long bp1 =
                *reinterpret_cast<const unsigned long long*>(&Bs[kk * 132 + tx * 4 + 2]);
            unsigned long long bp2 =
                *reinterpret_cast<const unsigned long long*>(&Bs[kk * 132 + 64 + tx * 4]);
            unsigned long long bp3 =
                *reinterpret_cast<const unsigned long long*>(&Bs[kk * 132 + 64 + tx * 4 + 2]);
#pragma unroll
            for (int i = 0; i < 8; i++) {
                unsigned long long aa = pack_dup(av[i]);
                ffma2(pacc[i][0], aa, bp0);
                ffma2(pacc[i][1], aa, bp1);
                ffma2(pacc[i][2], aa, bp2);
                ffma2(pacc[i][3], aa, bp3);
            }
        }
        __syncthreads();
    }

    // Epilogue: scatter to q/k/v [b][h][n][d]
    float* dst = (t3 == 0) ? g_q : ((t3 == 1) ? g_k : g_v);
    const float scale = (t3 == 0) ? 0.17677669529663687f : 1.0f;  // 32^-0.5

#pragma unroll
    for (int ih = 0; ih < 2; ih++) {
#pragma unroll
        for (int i = 0; i < 4; i++) {
            int r = ih * 64 + ty * 4 + i;
            int gm = m0 + r;
            int b = gm / 49;
            int n = gm - b * 49;
#pragma unroll
            for (int jh = 0; jh < 2; jh++) {
                int c = jh * 64 + tx * 4;   // within one head (32-aligned block)
                int h = c >> 5;
                int d = c & 31;
                unsigned long long p0 = pacc[ih * 4 + i][jh * 2 + 0];
                unsigned long long p1 = pacc[ih * 4 + i][jh * 2 + 1];
                float4 o;
                o.x = (lo32(p0) + bias[t3 * 128 + c + 0]) * scale;
                o.y = (hi32(p0) + bias[t3 * 128 + c + 1]) * scale;
                o.z = (lo32(p1) + bias[t3 * 128 + c + 2]) * scale;
                o.w = (hi32(p1) + bias[t3 * 128 + c + 3]) * scale;
                *reinterpret_cast<float4*>(
                    &dst[(((size_t)b * H_HEADS + h) * N_TOK + n) * HD + d]) = o;
            }
        }
    }
}

// ---------------------------------------------------------------------------
// Attention: one CTA per (window b, head h). 128 threads (unchanged, proven).
// ---------------------------------------------------------------------------
__global__ __launch_bounds__(128) void attn_kernel() {
    __shared__ float qs[56 * 33];    // [n][k]
    __shared__ float ks_t[32 * 68];  // [k][m]  (transposed K)
    __shared__ float vs[49 * 36];    // [m][d]
    __shared__ float S[56 * 53];     // [n][m]

    const int tid = threadIdx.x;
    const int b = blockIdx.x;
    const int h = blockIdx.y;

    const size_t base4 = (((size_t)b * H_HEADS + h) * N_TOK) * 8;  // float4 units
    const float4* q4 = reinterpret_cast<const float4*>(g_q);
    const float4* k4p = reinterpret_cast<const float4*>(g_k);
    const float4* v4 = reinterpret_cast<const float4*>(g_v);
    for (int f = tid; f < 49 * 8; f += 128) {
        int row = f >> 3;
        int c4 = f & 7;
        float4 vq = q4[base4 + f];
        float4 vk = k4p[base4 + f];
        float4 vv = v4[base4 + f];
        int o = row * 33 + c4 * 4;
        qs[o + 0] = vq.x; qs[o + 1] = vq.y; qs[o + 2] = vq.z; qs[o + 3] = vq.w;
        ks_t[(c4 * 4 + 0) * 68 + row] = vk.x;
        ks_t[(c4 * 4 + 1) * 68 + row] = vk.y;
        ks_t[(c4 * 4 + 2) * 68 + row] = vk.z;
        ks_t[(c4 * 4 + 3) * 68 + row] = vk.w;
        *reinterpret_cast<float4*>(&vs[row * 36 + c4 * 4]) = vv;
    }
    __syncthreads();

    const int rowg = tid >> 4;   // 0..7
    const int colg = tid & 15;   // 0..15

    {
        float acc[7][4];
#pragma unroll
        for (int a = 0; a < 7; a++)
#pragma unroll
            for (int j = 0; j < 4; j++) acc[a][j] = 0.0f;

#pragma unroll 4
        for (int k = 0; k < 32; k++) {
            float qf[7];
#pragma unroll
            for (int a = 0; a < 7; a++) qf[a] = qs[(rowg * 7 + a) * 33 + k];
            float4 kf = *reinterpret_cast<const float4*>(&ks_t[k * 68 + colg * 4]);
#pragma unroll
            for (int a = 0; a < 7; a++) {
                acc[a][0] = fmaf(qf[a], kf.x, acc[a][0]);
                acc[a][1] = fmaf(qf[a], kf.y, acc[a][1]);
                acc[a][2] = fmaf(qf[a], kf.z, acc[a][2]);
                acc[a][3] = fmaf(qf[a], kf.w, acc[a][3]);
            }
        }

        const float* cb = g_comb + ((size_t)((b & 63) * H_HEADS + h)) * 2401;
#pragma unroll
        for (int a = 0; a < 7; a++) {
            int n = rowg * 7 + a;
            if (n < 49) {
#pragma unroll
                for (int j = 0; j < 4; j++) {
                    int m = colg * 4 + j;
                    if (m < 49) S[n * 53 + m] = acc[a][j] + cb[n * 49 + m];
                }
            }
        }
    }
    __syncthreads();

    if (tid < 49) {
        float mx = -1e30f;
#pragma unroll 7
        for (int m = 0; m < 49; m++) mx = fmaxf(mx, S[tid * 53 + m]);
        float s = 0.0f;
#pragma unroll 7
        for (int m = 0; m < 49; m++) {
            float e = __expf(S[tid * 53 + m] - mx);
            S[tid * 53 + m] = e;
            s += e;
        }
        float inv = 1.0f / s;
#pragma unroll 7
        for (int m = 0; m < 49; m++) S[tid * 53 + m] *= inv;
    }
    __syncthreads();

    {
        float acc2[7][2];
#pragma unroll
        for (int a = 0; a < 7; a++) { acc2[a][0] = 0.0f; acc2[a][1] = 0.0f; }

#pragma unroll 7
        for (int m = 0; m < 49; m++) {
            float2 vf = *reinterpret_cast<const float2*>(&vs[m * 36 + colg * 2]);
#pragma unroll
            for (int a = 0; a < 7; a++) {
                float pf = S[(rowg * 7 + a) * 53 + m];
                acc2[a][0] = fmaf(pf, vf.x, acc2[a][0]);
                acc2[a][1] = fmaf(pf, vf.y, acc2[a][1]);
            }
        }

#pragma unroll
        for (int a = 0; a < 7; a++) {
            int n = rowg * 7 + a;
            if (n < 49) {
                float2 o = make_float2(acc2[a][0], acc2[a][1]);
                *reinterpret_cast<float2*>(
                    &g_ao[((size_t)b * N_TOK + n) * C_DIM + h * HD + colg * 2]) = o;
            }
        }
    }
}

// ---------------------------------------------------------------------------
// Proj GEMM (fp32, FFMA2 inner loop): A = g_ao [M,128], B = proj_w [128,128]
// ---------------------------------------------------------------------------
__global__ __launch_bounds__(256) void proj_gemm(const float* __restrict__ B,
                                                 const float* __restrict__ bias,
                                                 float* __restrict__ out) {
    __shared__ float As[32 * 132];
    __shared__ float Bs[32 * 132];

    const int tid = threadIdx.x;
    const int tx = tid & 15;
    const int ty = tid >> 4;
    const int m0 = blockIdx.x * 128;

    unsigned long long pacc[8][4];
#pragma unroll
    for (int i = 0; i < 8; i++)
#pragma unroll
        for (int j = 0; j < 4; j++) pacc[i][j] = 0ull;

    const float4* A4 = reinterpret_cast<const float4*>(g_ao);
    const float4* B4 = reinterpret_cast<const float4*>(B);

    for (int kc = 0; kc < 128; kc += 32) {
#pragma unroll
        for (int t = 0; t < 4; t++) {
            int flat = tid + t * 256;
            int m = flat >> 3;
            int k4 = flat & 7;
            float4 v = A4[(size_t)(m0 + m) * 32 + (kc >> 2) + k4];
            As[(k4 * 4 + 0) * 132 + m] = v.x;
            As[(k4 * 4 + 1) * 132 + m] = v.y;
            As[(k4 * 4 + 2) * 132 + m] = v.z;
            As[(k4 * 4 + 3) * 132 + m] = v.w;
        }
#pragma unroll
        for (int t = 0; t < 4; t++) {
            int flat = tid + t * 256;
            int kk = flat >> 5;
            int n4 = flat & 31;
            float4 v = B4[(size_t)(kc + kk) * 32 + n4];
            *reinterpret_cast<float4*>(&Bs[kk * 132 + n4 * 4]) = v;
        }
        __syncthreads();

#pragma unroll 8
        for (int kk = 0; kk < 32; kk++) {
            float av[8];
            *reinterpret_cast<float4*>(&av[0]) =
                *reinterpret_cast<const float4*>(&As[kk * 132 + ty * 4]);
            *reinterpret_cast<float4*>(&av[4]) =
                *reinterpret_cast<const float4*>(&As[kk * 132 + 64 + ty * 4]);
            unsigned long long bp0 =
                *reinterpret_cast<const unsigned long long*>(&Bs[kk * 132 + tx * 4]);
            unsigned long long bp1 =
                *reinterpret_cast<const unsigned long long*>(&Bs[kk * 132 + tx * 4 + 2]);
            unsigned long long bp2 =
                *reinterpret_cast<const unsigned long long*>(&Bs[kk * 132 + 64 + tx * 4]);
            unsigned long long bp3 =
                *reinterpret_cast<const unsigned long long*>(&Bs[kk * 132 + 64 + tx * 4 + 2]);
#pragma unroll
            for (int i = 0; i < 8; i++) {
                unsigned long long aa = pack_dup(av[i]);
                ffma2(pacc[i][0], aa, bp0);
                ffma2(pacc[i][1], aa, bp1);
                ffma2(pacc[i][2], aa, bp2);
                ffma2(pacc[i][3], aa, bp3);
            }
        }
        __syncthreads();
    }

#pragma unroll
    for (int ih = 0; ih < 2; ih++) {
#pragma unroll
        for (int i = 0; i < 4; i++) {
            int r = ih * 64 + ty * 4 + i;
            size_t gm = (size_t)m0 + r;
#pragma unroll
            for (int jh = 0; jh < 2; jh++) {
                int c = jh * 64 + tx * 4;
                unsigned long long p0 = pacc[ih * 4 + i][jh * 2 + 0];
                unsigned long long p1 = pacc[ih * 4 + i][jh * 2 + 1];
                float4 o;
                o.x = lo32(p0) + bias[c + 0];
                o.y = hi32(p0) + bias[c + 1];
                o.z = lo32(p1) + bias[c + 2];
                o.w = hi32(p1) + bias[c + 3];
                *reinterpret_cast<float4*>(&out[gm * C_DIM + c]) = o;
            }
        }
    }
}

// ---------------------------------------------------------------------------
extern "C" void kernel_launch(void* const* d_in, const int* in_sizes, int n_in,
                              void* d_out, int out_size) {
    const float* x          = (const float*)d_in[0];
    const float* mask       = (const float*)d_in[1];
    const float* qkv_w      = (const float*)d_in[2];
    const float* qkv_b      = (const float*)d_in[3];
    const float* proj_w     = (const float*)d_in[4];
    const float* proj_b     = (const float*)d_in[5];
    const float* bias_table = (const float*)d_in[6];
    const int*   rel32      = (const int*)d_in[7];

    int idx_stride = (in_sizes[7] >= 2401 * 2) ? 2 : 1;

    comb_kernel<<<dim3(64, H_HEADS), 256>>>(mask, bias_table, rel32, idx_stride);
    qkv_gemm<<<dim3(M_ROWS / 128, 3), 256>>>(x, qkv_w, qkv_b);
    attn_kernel<<<dim3(B_WIN, H_HEADS), 128>>>();
    proj_gemm<<<dim3(M_ROWS / 128, 1), 256>>>(proj_w, proj_b, (float*)d_out);
}

// round 9
// speedup vs baseline: 1.2623x; 1.0083x over previous
#include <cuda_runtime.h>
#include <cstdint>

// Problem constants
#define B_WIN 4096
#define N_TOK 49
#define C_DIM 128
#define H_HEADS 4
#define HD 32
#define M_ROWS (B_WIN * N_TOK)   // 200704 = 1568 * 128 exactly

// Scratch: __device__ globals (no allocations allowed)
__device__ float g_q[B_WIN * H_HEADS * N_TOK * HD];   // [b][h][n][d]
__device__ float g_k[B_WIN * H_HEADS * N_TOK * HD];
__device__ float g_v[B_WIN * H_HEADS * N_TOK * HD];
__device__ float g_ao[(size_t)M_ROWS * C_DIM];        // attention output [b*n][c]
__device__ float g_comb[64 * H_HEADS * N_TOK * N_TOK]; // bias+mask [w][h][n][m]

// ---------------------------------------------------------------------------
// comb precompute: comb[w][h][e] = bias_table[rel_index[e]][h] + mask[w][e]
// ---------------------------------------------------------------------------
__global__ void comb_kernel(const float* __restrict__ mask,
                            const float* __restrict__ bias_table,
                            const int* __restrict__ rel32, int idx_stride) {
    const int w = blockIdx.x;
    const int h = blockIdx.y;
    float* dst = g_comb + ((size_t)w * H_HEADS + h) * 2401;
    const float* msk = mask + (size_t)w * 2401;
    for (int e = threadIdx.x; e < 2401; e += blockDim.x) {
        int idx = rel32[e * idx_stride];
        dst[e] = bias_table[idx * H_HEADS + h] + msk[e];
    }
}

// ---------------------------------------------------------------------------
// Packed fp32x2 helpers (Blackwell FFMA2). Per-lane math is exact fp32 FMA.
// ---------------------------------------------------------------------------
__device__ __forceinline__ unsigned long long pack_dup(float a) {
    unsigned long long r;
    uint32_t ai = __float_as_uint(a);
    asm("mov.b64 %0, {%1, %1};" : "=l"(r) : "r"(ai));
    return r;
}
__device__ __forceinline__ void ffma2(unsigned long long& c, unsigned long long a,
                                      unsigned long long b) {
    asm("fma.rn.f32x2 %0, %1, %2, %0;" : "+l"(c) : "l"(a), "l"(b));
}
__device__ __forceinline__ float lo32(unsigned long long v) {
    return __uint_as_float((uint32_t)v);
}
__device__ __forceinline__ float hi32(unsigned long long v) {
    return __uint_as_float((uint32_t)(v >> 32));
}

// ---------------------------------------------------------------------------
// QKV GEMM (fp32, FFMA2): unchanged from R8 (proven).
// ---------------------------------------------------------------------------
__global__ __launch_bounds__(256) void qkv_gemm(const float* __restrict__ A,
                                                const float* __restrict__ B,
                                                const float* __restrict__ bias) {
    __shared__ float As[32 * 132];  // [k][m], padded stride 132
    __shared__ float Bs[32 * 132];  // [k][n], padded stride 132

    const int tid = threadIdx.x;
    const int tx = tid & 15;
    const int ty = tid >> 4;
    const int m0 = blockIdx.x * 128;
    const int t3 = blockIdx.y;      // 0=q, 1=k, 2=v

    unsigned long long pacc[8][4];
#pragma unroll
    for (int i = 0; i < 8; i++)
#pragma unroll
        for (int j = 0; j < 4; j++) pacc[i][j] = 0ull;

    const float4* A4 = reinterpret_cast<const float4*>(A);
    const float4* B4 = reinterpret_cast<const float4*>(B);

    for (int kc = 0; kc < 128; kc += 32) {
#pragma unroll
        for (int t = 0; t < 4; t++) {
            int flat = tid + t * 256;
            int m = flat >> 3;
            int k4 = flat & 7;
            float4 v = A4[(size_t)(m0 + m) * 32 + (kc >> 2) + k4];
            As[(k4 * 4 + 0) * 132 + m] = v.x;
            As[(k4 * 4 + 1) * 132 + m] = v.y;
            As[(k4 * 4 + 2) * 132 + m] = v.z;
            As[(k4 * 4 + 3) * 132 + m] = v.w;
        }
#pragma unroll
        for (int t = 0; t < 4; t++) {
            int flat = tid + t * 256;
            int kk = flat >> 5;
            int n4 = flat & 31;
            float4 v = B4[(size_t)(kc + kk) * 96 + t3 * 32 + n4];
            *reinterpret_cast<float4*>(&Bs[kk * 132 + n4 * 4]) = v;
        }
        __syncthreads();

#pragma unroll 8
        for (int kk = 0; kk < 32; kk++) {
            float av[8];
            *reinterpret_cast<float4*>(&av[0]) =
                *reinterpret_cast<const float4*>(&As[kk * 132 + ty * 4]);
            *reinterpret_cast<float4*>(&av[4]) =
                *reinterpret_cast<const float4*>(&As[kk * 132 + 64 + ty * 4]);
            unsigned long long bp0 =
                *reinterpret_cast<const unsigned long long*>(&Bs[kk * 132 + tx * 4]);
            unsigned long long bp1 =
                *reinterpret_cast<const unsigned long long*>(&Bs[kk * 132 + tx * 4 + 2]);
            unsigned long long bp2 =
                *reinterpret_cast<const unsigned long long*>(&Bs[kk * 132 + 64 + tx * 4]);
            unsigned long long bp3 =
                *reinterpret_cast<const unsigned long long*>(&Bs[kk * 132 + 64 + tx * 4 + 2]);
#pragma unroll
            for (int i = 0; i < 8; i++) {
                unsigned long long aa = pack_dup(av[i]);
                ffma2(pacc[i][0], aa, bp0);
                ffma2(pacc[i][1], aa, bp1);
                ffma2(pacc[i][2], aa, bp2);
                ffma2(pacc[i][3], aa, bp3);
            }
        }
        __syncthreads();
    }

    float* dst = (t3 == 0) ? g_q : ((t3 == 1) ? g_k : g_v);
    const float scale = (t3 == 0) ? 0.17677669529663687f : 1.0f;  // 32^-0.5

#pragma unroll
    for (int ih = 0; ih < 2; ih++) {
#pragma unroll
        for (int i = 0; i < 4; i++) {
            int r = ih * 64 + ty * 4 + i;
            int gm = m0 + r;
            int b = gm / 49;
            int n = gm - b * 49;
#pragma unroll
            for (int jh = 0; jh < 2; jh++) {
                int c = jh * 64 + tx * 4;
                int h = c >> 5;
                int d = c & 31;
                unsigned long long p0 = pacc[ih * 4 + i][jh * 2 + 0];
                unsigned long long p1 = pacc[ih * 4 + i][jh * 2 + 1];
                float4 o;
                o.x = (lo32(p0) + bias[t3 * 128 + c + 0]) * scale;
                o.y = (hi32(p0) + bias[t3 * 128 + c + 1]) * scale;
                o.z = (lo32(p1) + bias[t3 * 128 + c + 2]) * scale;
                o.w = (hi32(p1) + bias[t3 * 128 + c + 3]) * scale;
                *reinterpret_cast<float4*>(
                    &dst[(((size_t)b * H_HEADS + h) * N_TOK + n) * HD + d]) = o;
            }
        }
    }
}

// ---------------------------------------------------------------------------
// Attention v3: shuffle softmax (register-resident), FFMA2 S-phase.
// One CTA per (window b, head h). 128 threads.
// rowg = tid>>4 (0..7, rows rowg*7..+6), colg = tid&15 (cols colg*4..+3).
// The 16 colg threads of a row group are lanes [rowg*16 & 31 ..+15] of one
// warp -> shfl.xor width 16 reduces across the row.
// ---------------------------------------------------------------------------
__global__ __launch_bounds__(128) void attn_kernel() {
    __shared__ float qs[56 * 33];    // [n][k]
    __shared__ float ks_t[32 * 68];  // [k][m]  (transposed K)
    __shared__ float vs[49 * 36];    // [m][d]
    __shared__ float P[56 * 53];     // normalized probs [n][m]

    const int tid = threadIdx.x;
    const int b = blockIdx.x;
    const int h = blockIdx.y;

    const size_t base4 = (((size_t)b * H_HEADS + h) * N_TOK) * 8;  // float4 units
    const float4* q4 = reinterpret_cast<const float4*>(g_q);
    const float4* k4p = reinterpret_cast<const float4*>(g_k);
    const float4* v4 = reinterpret_cast<const float4*>(g_v);
    for (int f = tid; f < 49 * 8; f += 128) {
        int row = f >> 3;
        int c4 = f & 7;
        float4 vq = q4[base4 + f];
        float4 vk = k4p[base4 + f];
        float4 vv = v4[base4 + f];
        int o = row * 33 + c4 * 4;
        qs[o + 0] = vq.x; qs[o + 1] = vq.y; qs[o + 2] = vq.z; qs[o + 3] = vq.w;
        ks_t[(c4 * 4 + 0) * 68 + row] = vk.x;
        ks_t[(c4 * 4 + 1) * 68 + row] = vk.y;
        ks_t[(c4 * 4 + 2) * 68 + row] = vk.z;
        ks_t[(c4 * 4 + 3) * 68 + row] = vk.w;
        *reinterpret_cast<float4*>(&vs[row * 36 + c4 * 4]) = vv;
    }
    __syncthreads();

    const int rowg = tid >> 4;   // 0..7
    const int colg = tid & 15;   // 0..15

    // --- S = q k^T (FFMA2 over col pairs) ---
    unsigned long long pacc[7][2];
#pragma unroll
    for (int a = 0; a < 7; a++) { pacc[a][0] = 0ull; pacc[a][1] = 0ull; }

#pragma unroll 4
    for (int k = 0; k < 32; k++) {
        unsigned long long kp0 =
            *reinterpret_cast<const unsigned long long*>(&ks_t[k * 68 + colg * 4]);
        unsigned long long kp1 =
            *reinterpret_cast<const unsigned long long*>(&ks_t[k * 68 + colg * 4 + 2]);
#pragma unroll
        for (int a = 0; a < 7; a++) {
            unsigned long long qq = pack_dup(qs[(rowg * 7 + a) * 33 + k]);
            ffma2(pacc[a][0], qq, kp0);
            ffma2(pacc[a][1], qq, kp1);
        }
    }

    // --- fused bias add + softmax via half-warp shuffles, write P ---
    {
        const float* cb = g_comb + ((size_t)((b & 63) * H_HEADS + h)) * 2401;
#pragma unroll
        for (int a = 0; a < 7; a++) {
            int n = rowg * 7 + a;
            float v0 = lo32(pacc[a][0]);
            float v1 = hi32(pacc[a][0]);
            float v2 = lo32(pacc[a][1]);
            float v3 = hi32(pacc[a][1]);
            int m0c = colg * 4;
            // add comb bias for valid (n,m); invalid -> -1e30 so it never wins max
            if (n < 49) {
                const float* cr = cb + n * 49 + m0c;
                v0 = (m0c + 0 < 49) ? v0 + cr[0] : -1e30f;
                v1 = (m0c + 1 < 49) ? v1 + cr[1] : -1e30f;
                v2 = (m0c + 2 < 49) ? v2 + cr[2] : -1e30f;
                v3 = (m0c + 3 < 49) ? v3 + cr[3] : -1e30f;
            } else {
                v0 = v1 = v2 = v3 = -1e30f;  // dead row, keep lanes converged
            }
            float mx = fmaxf(fmaxf(v0, v1), fmaxf(v2, v3));
#pragma unroll
            for (int ofs = 1; ofs < 16; ofs <<= 1)
                mx = fmaxf(mx, __shfl_xor_sync(0xffffffffu, mx, ofs, 16));
            float e0 = __expf(v0 - mx);
            float e1 = __expf(v1 - mx);
            float e2 = __expf(v2 - mx);
            float e3 = __expf(v3 - mx);
            float sm = (e0 + e1) + (e2 + e3);
#pragma unroll
            for (int ofs = 1; ofs < 16; ofs <<= 1)
                sm += __shfl_xor_sync(0xffffffffu, sm, ofs, 16);
            float inv = 1.0f / sm;
            // write normalized probs (guard m<49; n<56 always in-bounds)
            float* pr = &P[n * 53 + m0c];
            if (m0c + 0 < 49) pr[0] = e0 * inv;
            if (m0c + 1 < 49) pr[1] = e1 * inv;
            if (m0c + 2 < 49) pr[2] = e2 * inv;
            if (m0c + 3 < 49) pr[3] = e3 * inv;
        }
    }
    __syncthreads();

    // --- O = P v : each thread 7 rows x 2 cols ---
    {
        float acc2[7][2];
#pragma unroll
        for (int a = 0; a < 7; a++) { acc2[a][0] = 0.0f; acc2[a][1] = 0.0f; }

#pragma unroll 7
        for (int m = 0; m < 49; m++) {
            float2 vf = *reinterpret_cast<const float2*>(&vs[m * 36 + colg * 2]);
#pragma unroll
            for (int a = 0; a < 7; a++) {
                float pf = P[(rowg * 7 + a) * 53 + m];
                acc2[a][0] = fmaf(pf, vf.x, acc2[a][0]);
                acc2[a][1] = fmaf(pf, vf.y, acc2[a][1]);
            }
        }

#pragma unroll
        for (int a = 0; a < 7; a++) {
            int n = rowg * 7 + a;
            if (n < 49) {
                float2 o = make_float2(acc2[a][0], acc2[a][1]);
                *reinterpret_cast<float2*>(
                    &g_ao[((size_t)b * N_TOK + n) * C_DIM + h * HD + colg * 2]) = o;
            }
        }
    }
}

// ---------------------------------------------------------------------------
// Proj GEMM (fp32, FFMA2): unchanged from R8 (proven).
// ---------------------------------------------------------------------------
__global__ __launch_bounds__(256) void proj_gemm(const float* __restrict__ B,
                                                 const float* __restrict__ bias,
                                                 float* __restrict__ out) {
    __shared__ float As[32 * 132];
    __shared__ float Bs[32 * 132];

    const int tid = threadIdx.x;
    const int tx = tid & 15;
    const int ty = tid >> 4;
    const int m0 = blockIdx.x * 128;

    unsigned long long pacc[8][4];
#pragma unroll
    for (int i = 0; i < 8; i++)
#pragma unroll
        for (int j = 0; j < 4; j++) pacc[i][j] = 0ull;

    const float4* A4 = reinterpret_cast<const float4*>(g_ao);
    const float4* B4 = reinterpret_cast<const float4*>(B);

    for (int kc = 0; kc < 128; kc += 32) {
#pragma unroll
        for (int t = 0; t < 4; t++) {
            int flat = tid + t * 256;
            int m = flat >> 3;
            int k4 = flat & 7;
            float4 v = A4[(size_t)(m0 + m) * 32 + (kc >> 2) + k4];
            As[(k4 * 4 + 0) * 132 + m] = v.x;
            As[(k4 * 4 + 1) * 132 + m] = v.y;
            As[(k4 * 4 + 2) * 132 + m] = v.z;
            As[(k4 * 4 + 3) * 132 + m] = v.w;
        }
#pragma unroll
        for (int t = 0; t < 4; t++) {
            int flat = tid + t * 256;
            int kk = flat >> 5;
            int n4 = flat & 31;
            float4 v = B4[(size_t)(kc + kk) * 32 + n4];
            *reinterpret_cast<float4*>(&Bs[kk * 132 + n4 * 4]) = v;
        }
        __syncthreads();

#pragma unroll 8
        for (int kk = 0; kk < 32; kk++) {
            float av[8];
            *reinterpret_cast<float4*>(&av[0]) =
                *reinterpret_cast<const float4*>(&As[kk * 132 + ty * 4]);
            *reinterpret_cast<float4*>(&av[4]) =
                *reinterpret_cast<const float4*>(&As[kk * 132 + 64 + ty * 4]);
            unsigned long long bp0 =
                *reinterpret_cast<const unsigned long long*>(&Bs[kk * 132 + tx * 4]);
            unsigned long long bp1 =
                *reinterpret_cast<const unsigned long long*>(&Bs[kk * 132 + tx * 4 + 2]);
            unsigned long long bp2 =
                *reinterpret_cast<const unsigned long long*>(&Bs[kk * 132 + 64 + tx * 4]);
            unsigned long long bp3 =
                *reinterpret_cast<const unsigned long long*>(&Bs[kk * 132 + 64 + tx * 4 + 2]);
#pragma unroll
            for (int i = 0; i < 8; i++) {
                unsigned long long aa = pack_dup(av[i]);
                ffma2(pacc[i][0], aa, bp0);
                ffma2(pacc[i][1], aa, bp1);
                ffma2(pacc[i][2], aa, bp2);
                ffma2(pacc[i][3], aa, bp3);
            }
        }
        __syncthreads();
    }

#pragma unroll
    for (int ih = 0; ih < 2; ih++) {
#pragma unroll
        for (int i = 0; i < 4; i++) {
            int r = ih * 64 + ty * 4 + i;
            size_t gm = (size_t)m0 + r;
#pragma unroll
            for (int jh = 0; jh < 2; jh++) {
                int c = jh * 64 + tx * 4;
                unsigned long long p0 = pacc[ih * 4 + i][jh * 2 + 0];
                unsigned long long p1 = pacc[ih * 4 + i][jh * 2 + 1];
                float4 o;
                o.x = lo32(p0) + bias[c + 0];
                o.y = hi32(p0) + bias[c + 1];
                o.z = lo32(p1) + bias[c + 2];
                o.w = hi32(p1) + bias[c + 3];
                *reinterpret_cast<float4*>(&out[gm * C_DIM + c]) = o;
            }
        }
    }
}

// ---------------------------------------------------------------------------
extern "C" void kernel_launch(void* const* d_in, const int* in_sizes, int n_in,
                              void* d_out, int out_size) {
    const float* x          = (const float*)d_in[0];
    const float* mask       = (const float*)d_in[1];
    const float* qkv_w      = (const float*)d_in[2];
    const float* qkv_b      = (const float*)d_in[3];
    const float* proj_w     = (const float*)d_in[4];
    const float* proj_b     = (const float*)d_in[5];
    const float* bias_table = (const float*)d_in[6];
    const int*   rel32      = (const int*)d_in[7];

    int idx_stride = (in_sizes[7] >= 2401 * 2) ? 2 : 1;

    comb_kernel<<<dim3(64, H_HEADS), 256>>>(mask, bias_table, rel32, idx_stride);
    qkv_gemm<<<dim3(M_ROWS / 128, 3), 256>>>(x, qkv_w, qkv_b);
    attn_kernel<<<dim3(B_WIN, H_HEADS), 128>>>();
    proj_gemm<<<dim3(M_ROWS / 128, 1), 256>>>(proj_w, proj_b, (float*)d_out);
}